// round 15
// baseline (speedup 1.0000x reference)
#include <cuda_runtime.h>
#include <cstdint>

#define BB   32
#define NN   2048
#define KNN  20

static __device__ __forceinline__ float lrelu(float v) { return v >= 0.0f ? v : 0.2f * v; }
#define FINF __int_as_float(0x7f800000)

__device__ uint32_t g_big[(size_t)BB * NN * NN];  // order-preserving dist keys (smaller = nearer)
__device__ float g_h  [(size_t)BB * NN * 128];
__device__ float g_P  [(size_t)BB * NN * 64];
__device__ float g_Q  [(size_t)BB * NN * 64];
__device__ float g_sq [BB * NN];
__device__ int   g_idx[BB * NN * KNN];
__device__ float4 g_pos4[BB * NN];
__device__ float g_pmax[(size_t)BB * 16 * 1024];
__device__ float g_psum[(size_t)BB * 16 * 1024];
__device__ float g_red[2 * BB * 1024 + 2 * BB * 64];

static __device__ __forceinline__ uint32_t fkey(float f) {
    uint32_t u = __float_as_uint(f);
    return (u & 0x80000000u) ? ~u : (u | 0x80000000u);
}

// element index mapping: GS=1: idx=i*32+lane ; GS=4: idx=(i>>2)*128+lane*4+(i&3)
template<int GS>
static __device__ __forceinline__ int elem_idx(int i, int lane) {
    return (GS == 1) ? (i * 32 + lane) : ((i >> 2) * 128 + lane * 4 + (i & 3));
}

// ---- warp-scope exact top-20-smallest (value, then index) ----
// All key loops fully unrolled (static indices) so u[64] stays in registers.
template<int GS>
static __device__ void wsel20(const uint32_t (&u)[64], int lane, uint32_t* Hw, int* slotp, int* out) {
    const unsigned FULL = 0xffffffffu;
    if (lane == 0) *slotp = 0;
    __syncwarp();
    uint32_t pref = 0;
    int need = KNN;
    bool done = false;
#pragma unroll
    for (int rnd = 0; rnd < 4; ++rnd) {
        if (!done) {
            const int shift = 24 - rnd * 8;
            // zero hist
#pragma unroll
            for (int z = 0; z < 8; ++z) Hw[z * 32 + lane] = 0;
            __syncwarp();
            // histogram pass (warp-aggregated smem atomics, static indices)
#pragma unroll
            for (int i = 0; i < 64; ++i) {
                bool mem = (rnd == 0) || ((u[i] >> (shift + 8)) == pref);
                uint32_t bn = mem ? ((u[i] >> shift) & 255u) : 0x100u;
                unsigned same = __match_any_sync(FULL, bn);
                if (mem && lane == __ffs(same) - 1) atomicAdd(&Hw[bn], (uint32_t)__popc(same));
            }
            __syncwarp();
            // scan 256 bins (lane owns bins lane*8..lane*8+7)
            uint32_t h[8], tot = 0;
#pragma unroll
            for (int z = 0; z < 8; ++z) { h[z] = Hw[lane * 8 + z]; tot += h[z]; }
            uint32_t inc = tot;
#pragma unroll
            for (int off = 1; off < 32; off <<= 1) {
                uint32_t o = __shfl_up_sync(FULL, inc, off);
                if (lane >= off) inc += o;
            }
            uint32_t cum = inc - tot;
            int bsel = -1; uint32_t below = 0;
#pragma unroll
            for (int z = 0; z < 8; ++z) {
                if (bsel < 0 && cum < (uint32_t)need && (uint32_t)need <= cum + h[z]) {
                    bsel = lane * 8 + z; below = cum;
                }
                cum += h[z];
            }
            unsigned fb = __ballot_sync(FULL, bsel >= 0);
            int src = __ffs(fb) - 1;
            bsel = __shfl_sync(FULL, bsel, src);
            below = __shfl_sync(FULL, below, src);
            uint32_t eqT = Hw[bsel];
            // emit bins strictly below boundary
#pragma unroll
            for (int i = 0; i < 64; ++i) {
                bool mem = (rnd == 0) || ((u[i] >> (shift + 8)) == pref);
                if (mem && (int)((u[i] >> shift) & 255u) < bsel)
                    out[atomicAdd(slotp, 1)] = elem_idx<GS>(i, lane);
            }
            need -= (int)below;
            pref = (pref << 8) | (uint32_t)bsel;
            if ((uint32_t)need == eqT) {
                // take the whole boundary bin
#pragma unroll
                for (int i = 0; i < 64; ++i) {
                    bool mem = (rnd == 0) || ((u[i] >> (shift + 8)) == pref >> 8);
                    if (mem && (int)((u[i] >> shift) & 255u) == bsel)
                        out[atomicAdd(slotp, 1)] = elem_idx<GS>(i, lane);
                }
                done = true;
            }
        }
    }
    if (done) return;
    // exact full-key ties: key == pref; take smallest original indices
    uint64_t tm = 0;
#pragma unroll
    for (int i = 0; i < 64; ++i) if (u[i] == pref) tm |= 1ull << i;
#pragma unroll
    for (int g = 0; g < 64 / GS; ++g) {
        if (need > 0) {
            uint32_t gm = (uint32_t)((tm >> (g * GS)) & ((GS == 1) ? 1ull : 0xFull));
            int cnt = __popc(gm);
            int incc = cnt;
#pragma unroll
            for (int off = 1; off < 32; off <<= 1) {
                int o = __shfl_up_sync(FULL, incc, off);
                if (lane >= off) incc += o;
            }
            int base = incc - cnt;
            int total = __shfl_sync(FULL, incc, 31);
            int take = need - base;
            if (take < 0) take = 0;
            if (take > cnt) take = cnt;
            for (int k2 = 0; k2 < take; ++k2) {
                int w2 = __ffs(gm) - 1; gm &= gm - 1;
                out[atomicAdd(slotp, 1)] = elem_idx<GS>(g * GS + w2, lane);
            }
            need -= (total < need ? total : need);
        }
    }
}

__global__ void pospack_kernel(const float* __restrict__ x) {
    int i = blockIdx.x * 256 + threadIdx.x;
    float p0 = x[i * 6 + 0], p1 = x[i * 6 + 1], p2 = x[i * 6 + 2];
    g_pos4[i] = make_float4(p0, p1, p2, p0 * p0 + p1 * p1 + p2 * p2);
}

__global__ void __launch_bounds__(256, 2) knnsel_kernel() {
    __shared__ float4 pos[2048];
    __shared__ uint32_t hist[8][256];
    __shared__ int slot[8];
    int t = threadIdx.x, w = t >> 5, lane = t & 31;
    size_t rowBase = (size_t)blockIdx.x * 8;
    int b = (int)(rowBase >> 11);
    const float4* P = g_pos4 + (size_t)b * NN;
    for (int i = t; i < 2048; i += 256) pos[i] = P[i];
    __syncthreads();
    size_t row = rowBase + w;
    float4 q = pos[(int)(row & 2047)];
    uint32_t u[64];
#pragma unroll
    for (int i = 0; i < 64; ++i) {
        float4 p = pos[i * 32 + lane];
        float inner = q.x * p.x + q.y * p.y + q.z * p.z;
        u[i] = fkey(-((2.0f * inner - q.w) - p.w));
    }
    wsel20<1>(u, lane, hist[w], &slot[w], g_idx + row * KNN);
}

__global__ void __launch_bounds__(256, 2) topksel_kernel() {
    __shared__ uint32_t hist[8][256];
    __shared__ int slot[8];
    int t = threadIdx.x, w = t >> 5, lane = t & 31;
    size_t row = (size_t)blockIdx.x * 8 + w;
    const uint4* D = (const uint4*)(g_big + row * NN);
    uint32_t u[64];
#pragma unroll
    for (int j = 0; j < 16; ++j) {
        uint4 v = D[j * 32 + lane];
        u[j * 4 + 0] = v.x;
        u[j * 4 + 1] = v.y;
        u[j * 4 + 2] = v.z;
        u[j * 4 + 3] = v.w;
    }
    wsel20<4>(u, lane, hist[w], &slot[w], g_idx + row * KNN);
}

__global__ void pq1_kernel(const float* __restrict__ x, const float* __restrict__ W) {
    __shared__ float xsh[4][3];
    int pt = threadIdx.x >> 6, o = threadIdx.x & 63;
    size_t p = (size_t)blockIdx.x * 4 + pt;
    if (o < 3) xsh[pt][o] = x[p * 6 + o];
    __syncthreads();
    float sp = 0.f, sqv = 0.f;
#pragma unroll
    for (int c = 0; c < 3; ++c) {
        float xv = xsh[pt][c];
        float wd = W[o * 6 + c], wc = W[o * 6 + 3 + c];
        sp += xv * wd; sqv += xv * (wc - wd);
    }
    g_P[p * 64 + o] = sp;
    g_Q[p * 64 + o] = sqv;
}

__global__ void pq2_kernel(const float* __restrict__ W) {
    __shared__ float wd[64 * 65];
    __shared__ float wq[64 * 65];
    __shared__ float xsh[4][64];
    int t = threadIdx.x;
#pragma unroll
    for (int it = 0; it < 16; ++it) {
        int idx = t + it * 256;
        int c = idx & 63, o = idx >> 6;
        float a = W[o * 128 + c], bq = W[o * 128 + 64 + c];
        wd[c * 65 + o] = a;
        wq[c * 65 + o] = bq - a;
    }
    int pt = t >> 6, o = t & 63;
    size_t p = (size_t)blockIdx.x * 4 + pt;
    xsh[pt][o] = g_h[p * 128 + o];
    __syncthreads();
    float sp = 0.f, sqv = 0.f;
#pragma unroll 8
    for (int c = 0; c < 64; ++c) {
        float xv = xsh[pt][c];
        sp += xv * wd[c * 65 + o];
        sqv += xv * wq[c * 65 + o];
    }
    g_P[p * 64 + o] = sp;
    g_Q[p * 64 + o] = sqv;
}

__global__ void gather_kernel(int withSq, int outOff) {
    __shared__ int idxs[4][KNN];
    __shared__ float part[8];
    int pt = threadIdx.x >> 6, o = threadIdx.x & 63;
    size_t p = (size_t)blockIdx.x * 4 + pt;
    int b = (int)(p >> 11);
    if (o < KNN) idxs[pt][o] = g_idx[p * KNN + o];
    __syncthreads();
    float q = g_Q[p * 64 + o];
    float best = -FINF;
#pragma unroll
    for (int k = 0; k < KNN; ++k) {
        int m = idxs[pt][k];
        best = fmaxf(best, g_P[((size_t)b * NN + m) * 64 + o] + q);
    }
    best = lrelu(best);
    g_h[p * 128 + outOff + o] = best;
    if (withSq) {
        float s = best * best;
#pragma unroll
        for (int off = 16; off; off >>= 1) s += __shfl_xor_sync(0xffffffffu, s, off);
        if ((threadIdx.x & 31) == 0) part[threadIdx.x >> 5] = s;
        __syncthreads();
        if (o == 0) g_sq[p] = part[pt * 2] + part[pt * 2 + 1];
    }
}

__global__ void __launch_bounds__(256, 2) gram2_kernel() {
    extern __shared__ float sh[];
    float* As = sh;
    float* Bs = sh + 64 * 132;
    int b = blockIdx.y;
    int p = blockIdx.x;
    int ti = 0;
    while (p >= 16 - ti) { p -= 16 - ti; ++ti; }
    int tj = ti + p;
    int nBase = ti * 128, mBase = tj * 128;
    const float* X = g_h + (size_t)b * NN * 128;
    int tid = threadIdx.x;
#pragma unroll
    for (int it = 0; it < 32; ++it) {
        int idx = tid + it * 256;
        int r = idx >> 6, k = idx & 63;
        As[k * 132 + r] = X[(size_t)(nBase + r) * 128 + k];
        Bs[k * 132 + r] = X[(size_t)(mBase + r) * 128 + k];
    }
    __syncthreads();
    int tx = tid & 15, ty = tid >> 4;
    float acc[8][8] = {};
#pragma unroll 8
    for (int k = 0; k < 64; ++k) {
        float4 a0 = *(const float4*)&As[k * 132 + ty * 4];
        float4 a1 = *(const float4*)&As[k * 132 + 64 + ty * 4];
        float4 b0 = *(const float4*)&Bs[k * 132 + tx * 4];
        float4 b1 = *(const float4*)&Bs[k * 132 + 64 + tx * 4];
        float av[8] = {a0.x, a0.y, a0.z, a0.w, a1.x, a1.y, a1.z, a1.w};
        float bv[8] = {b0.x, b0.y, b0.z, b0.w, b1.x, b1.y, b1.z, b1.w};
#pragma unroll
        for (int u = 0; u < 8; ++u)
#pragma unroll
            for (int v = 0; v < 8; ++v) acc[u][v] += av[u] * bv[v];
    }
    const float* sqb = g_sq + b * NN;
    int rl[8], cl[8];
#pragma unroll
    for (int u = 0; u < 8; ++u) {
        rl[u] = (u < 4) ? ty * 4 + u : 64 + ty * 4 + (u - 4);
        cl[u] = (u < 4) ? tx * 4 + u : 64 + tx * 4 + (u - 4);
    }
    float qn[8], qm[8];
#pragma unroll
    for (int u = 0; u < 8; ++u) { qn[u] = sqb[nBase + rl[u]]; qm[u] = sqb[mBase + cl[u]]; }
#pragma unroll
    for (int u = 0; u < 8; ++u) {
        uint4 w0, w1;
        w0.x = fkey(-((2.0f * acc[u][0] - qn[u]) - qm[0]));
        w0.y = fkey(-((2.0f * acc[u][1] - qn[u]) - qm[1]));
        w0.z = fkey(-((2.0f * acc[u][2] - qn[u]) - qm[2]));
        w0.w = fkey(-((2.0f * acc[u][3] - qn[u]) - qm[3]));
        w1.x = fkey(-((2.0f * acc[u][4] - qn[u]) - qm[4]));
        w1.y = fkey(-((2.0f * acc[u][5] - qn[u]) - qm[5]));
        w1.z = fkey(-((2.0f * acc[u][6] - qn[u]) - qm[6]));
        w1.w = fkey(-((2.0f * acc[u][7] - qn[u]) - qm[7]));
        size_t base = ((size_t)b * NN + nBase + rl[u]) * NN + mBase;
        *(uint4*)&g_big[base + tx * 4]      = w0;
        *(uint4*)&g_big[base + 64 + tx * 4] = w1;
    }
    if (ti != tj) {
        __syncthreads();
        uint32_t* tru = (uint32_t*)sh;
#pragma unroll
        for (int u = 0; u < 8; ++u)
#pragma unroll
            for (int v = 0; v < 8; ++v)
                tru[cl[v] * 132 + rl[u]] = fkey(-((2.0f * acc[u][v] - qm[v]) - qn[u]));
        __syncthreads();
#pragma unroll
        for (int it = 0; it < 16; ++it) {
            int idx = tid + it * 256;
            int r = idx >> 5, c4 = idx & 31;
            uint4 wv = *(uint4*)&tru[r * 132 + c4 * 4];
            *(uint4*)&g_big[((size_t)b * NN + mBase + r) * NN + nBase + c4 * 4] = wv;
        }
    }
}

__global__ void __launch_bounds__(256, 2) w5p_kernel(const float* __restrict__ W5) {
    extern __shared__ float sh[];
    float* As = sh;
    float* Bs = sh + 64 * 132;
    int oBase = blockIdx.x * 128;
    int rt = blockIdx.y;
    int b  = blockIdx.z;
    size_t rowBase = (size_t)b * NN + rt * 128;
    int tid = threadIdx.x, tx = tid & 15, ty = tid >> 4;
    float acc[8][8] = {};
    for (int kb = 0; kb < 128; kb += 64) {
        __syncthreads();
#pragma unroll
        for (int it = 0; it < 32; ++it) {
            int idx = tid + it * 256;
            int r = idx >> 6, k = idx & 63;
            As[k * 132 + r] = g_h[(rowBase + r) * 128 + kb + k];
            Bs[k * 132 + r] = W5[(size_t)(oBase + r) * 128 + kb + k];
        }
        __syncthreads();
#pragma unroll 8
        for (int k = 0; k < 64; ++k) {
            float4 a0 = *(const float4*)&As[k * 132 + ty * 4];
            float4 a1 = *(const float4*)&As[k * 132 + 64 + ty * 4];
            float4 b0 = *(const float4*)&Bs[k * 132 + tx * 4];
            float4 b1 = *(const float4*)&Bs[k * 132 + 64 + tx * 4];
            float av[8] = {a0.x, a0.y, a0.z, a0.w, a1.x, a1.y, a1.z, a1.w};
            float bv[8] = {b0.x, b0.y, b0.z, b0.w, b1.x, b1.y, b1.z, b1.w};
#pragma unroll
            for (int u = 0; u < 8; ++u)
#pragma unroll
                for (int v = 0; v < 8; ++v) acc[u][v] += av[u] * bv[v];
        }
    }
    float cmax[8], csum[8];
#pragma unroll
    for (int v = 0; v < 8; ++v) { cmax[v] = -FINF; csum[v] = 0.f; }
#pragma unroll
    for (int u = 0; u < 8; ++u)
#pragma unroll
        for (int v = 0; v < 8; ++v) {
            float val = lrelu(acc[u][v]);
            cmax[v] = fmaxf(cmax[v], val);
            csum[v] += val;
        }
    __syncthreads();
    float* pmax = sh;
    float* psum = sh + 16 * 128;
#pragma unroll
    for (int v = 0; v < 8; ++v) {
        int c = (v < 4) ? tx * 4 + v : 64 + tx * 4 + (v - 4);
        pmax[ty * 128 + c] = cmax[v];
        psum[ty * 128 + c] = csum[v];
    }
    __syncthreads();
    if (tid < 128) {
        float m = -FINF, s = 0.f;
#pragma unroll
        for (int t2 = 0; t2 < 16; ++t2) {
            m = fmaxf(m, pmax[t2 * 128 + tid]);
            s += psum[t2 * 128 + tid];
        }
        size_t o = ((size_t)b * 16 + rt) * 1024 + oBase + tid;
        g_pmax[o] = m;
        g_psum[o] = s;
    }
}

__global__ void hreduce_kernel() {
    int t = blockIdx.x * 256 + threadIdx.x;
    int b = t >> 10, c = t & 1023;
    float m = -FINF, s = 0.f;
#pragma unroll
    for (int tile = 0; tile < 16; ++tile) {
        size_t idx = ((size_t)b * 16 + tile) * 1024 + c;
        m = fmaxf(m, g_pmax[idx]);
        s += g_psum[idx];
    }
    g_red[b * 1024 + c]         = m;
    g_red[32768 + b * 1024 + c] = s * (1.0f / NN);
}

__global__ void fbranch2_kernel(const float* __restrict__ x,
                                const float* __restrict__ W3,
                                const float* __restrict__ W4) {
    __shared__ float w3s[96];
    __shared__ float w4t[32 * 64];
    __shared__ float f1s[32][33];
    __shared__ float rmx[4][64], rsm[4][64];
    int b = blockIdx.x, t = threadIdx.x;
    if (t < 96) w3s[t] = W3[t];
    for (int it = t; it < 2048; it += 256) {
        int o = it & 63, j = it >> 6;
        w4t[j * 64 + o] = W4[o * 32 + j];
    }
    int o = t & 63, pg = t >> 6;
    float mx = -FINF, sm = 0.f;
    for (int n0 = 0; n0 < NN; n0 += 32) {
        __syncthreads();
#pragma unroll
        for (int e = 0; e < 4; ++e) {
            int idx = t + e * 256;
            int pp = idx >> 5, oo = idx & 31;
            const float* xp = x + ((size_t)b * NN + n0 + pp) * 6 + 3;
            float s = xp[0] * w3s[oo * 3] + xp[1] * w3s[oo * 3 + 1] + xp[2] * w3s[oo * 3 + 2];
            f1s[pp][oo] = lrelu(s);
        }
        __syncthreads();
#pragma unroll
        for (int q = 0; q < 8; ++q) {
            int pp = pg * 8 + q;
            float s = 0.f;
#pragma unroll
            for (int j2 = 0; j2 < 32; ++j2) s += f1s[pp][j2] * w4t[j2 * 64 + o];
            s = lrelu(s);
            mx = fmaxf(mx, s);
            sm += s;
        }
    }
    rmx[pg][o] = mx; rsm[pg][o] = sm;
    __syncthreads();
    if (t < 64) {
        float m = fmaxf(fmaxf(rmx[0][t], rmx[1][t]), fmaxf(rmx[2][t], rmx[3][t]));
        float s = rsm[0][t] + rsm[1][t] + rsm[2][t] + rsm[3][t];
        g_red[65536 + b * 64 + t] = m;
        g_red[67584 + b * 64 + t] = s * (1.0f / NN);
    }
}

__global__ void mlp2_kernel(const float* __restrict__ L1,
                            const float* __restrict__ L2w, const float* __restrict__ L2b,
                            const float* __restrict__ L3w, const float* __restrict__ L3b,
                            float* __restrict__ out) {
    __shared__ float z[2176];
    __shared__ float z1[128];
    __shared__ float z2[64];
    int b = blockIdx.x, t = threadIdx.x, w = t >> 5, lane = t & 31;
    for (int i = t; i < 2176; i += 256) {
        float v;
        if (i < 1024)      v = g_red[b * 1024 + i];
        else if (i < 2048) v = g_red[32768 + b * 1024 + (i - 1024)];
        else if (i < 2112) v = g_red[65536 + b * 64 + (i - 2048)];
        else               v = g_red[67584 + b * 64 + (i - 2112)];
        z[i] = v;
    }
    __syncthreads();
    for (int r = w; r < 128; r += 8) {
        const float* wt = L1 + (size_t)r * 2176;
        float s = 0.f;
        for (int j = lane; j < 2176; j += 32) s += z[j] * wt[j];
#pragma unroll
        for (int off = 16; off; off >>= 1) s += __shfl_xor_sync(0xffffffffu, s, off);
        if (lane == 0) z1[r] = lrelu(s);
    }
    __syncthreads();
    for (int r = w; r < 64; r += 8) {
        float s = 0.f;
#pragma unroll
        for (int j = lane; j < 128; j += 32) s += z1[j] * L2w[r * 128 + j];
#pragma unroll
        for (int off = 16; off; off >>= 1) s += __shfl_xor_sync(0xffffffffu, s, off);
        if (lane == 0) z2[r] = lrelu(s + L2b[r]);
    }
    __syncthreads();
    for (int r = w; r < 40; r += 8) {
        float s = 0.f;
#pragma unroll
        for (int j = lane; j < 64; j += 32) s += z2[j] * L3w[r * 64 + j];
#pragma unroll
        for (int off = 16; off; off >>= 1) s += __shfl_xor_sync(0xffffffffu, s, off);
        if (lane == 0) out[b * 40 + r] = s + L3b[r];
    }
}

extern "C" void kernel_launch(void* const* d_in, const int* in_sizes, int n_in,
                              void* d_out, int out_size) {
    const float* x   = (const float*)d_in[0];
    const float* W1  = (const float*)d_in[1];
    const float* W2  = (const float*)d_in[2];
    const float* W5  = (const float*)d_in[3];
    const float* W3  = (const float*)d_in[4];
    const float* W4  = (const float*)d_in[5];
    const float* L1  = (const float*)d_in[6];
    const float* L2w = (const float*)d_in[7];
    const float* L2b = (const float*)d_in[8];
    const float* L3w = (const float*)d_in[9];
    const float* L3b = (const float*)d_in[10];
    float* out = (float*)d_out;

    const int PTS = BB * NN;
    const int GEMM_SMEM = 2 * 64 * 132 * (int)sizeof(float);
    static int attrDone = 0;
    if (!attrDone) {
        cudaFuncSetAttribute(gram2_kernel, cudaFuncAttributeMaxDynamicSharedMemorySize, GEMM_SMEM);
        cudaFuncSetAttribute(w5p_kernel,   cudaFuncAttributeMaxDynamicSharedMemorySize, GEMM_SMEM);
        attrDone = 1;
    }

    // order keeps knnsel at capture slot (index 3) for ncu attribution
    pospack_kernel<<<PTS / 256, 256>>>(x);
    pq1_kernel<<<PTS / 4, 256>>>(x, W1);
    fbranch2_kernel<<<BB, 256>>>(x, W3, W4);
    knnsel_kernel<<<PTS / 8, 256>>>();
    gather_kernel<<<PTS / 4, 256>>>(1, 0);
    { dim3 grid(136, BB); gram2_kernel<<<grid, 256, GEMM_SMEM>>>(); }
    topksel_kernel<<<PTS / 8, 256>>>();
    pq2_kernel<<<PTS / 4, 256>>>(W2);
    gather_kernel<<<PTS / 4, 256>>>(0, 64);
    { dim3 grid(8, 16, BB); w5p_kernel<<<grid, 256, GEMM_SMEM>>>(W5); }
    hreduce_kernel<<<128, 256>>>();
    mlp2_kernel<<<BB, 256>>>(L1, L2w, L2b, L3w, L3b, out);
}

// round 16
// speedup vs baseline: 1.7630x; 1.7630x over previous
#include <cuda_runtime.h>
#include <cstdint>

#define BB   32
#define NN   2048
#define KNN  20
#define CANDMAX 248

static __device__ __forceinline__ float lrelu(float v) { return v >= 0.0f ? v : 0.2f * v; }
#define FINF __int_as_float(0x7f800000)

__device__ uint32_t g_big[(size_t)BB * NN * NN];  // order-preserving dist keys (smaller = nearer)
__device__ float g_h  [(size_t)BB * NN * 128];
__device__ float g_P  [(size_t)BB * NN * 64];
__device__ float g_Q  [(size_t)BB * NN * 64];
__device__ float g_sq [BB * NN];
__device__ int   g_idx[BB * NN * KNN];
__device__ float4 g_pos4[BB * NN];
__device__ float g_pmax[(size_t)BB * 16 * 1024];
__device__ float g_psum[(size_t)BB * 16 * 1024];
__device__ float g_red[2 * BB * 1024 + 2 * BB * 64];

static __device__ __forceinline__ uint32_t fkey(float f) {
    uint32_t u = __float_as_uint(f);
    return (u & 0x80000000u) ? ~u : (u | 0x80000000u);
}

static __device__ __forceinline__ uint32_t umin2(uint32_t a, uint32_t b) { return a < b ? a : b; }
static __device__ __forceinline__ uint32_t umax2(uint32_t a, uint32_t b) { return a > b ? a : b; }

// ascending bitonic sort of one value per lane; returns rank-20 value (0-based)
static __device__ __forceinline__ uint32_t warp_rank20(uint32_t v, int lane) {
    const unsigned FULL = 0xffffffffu;
#pragma unroll
    for (int k = 2; k <= 32; k <<= 1) {
#pragma unroll
        for (int j = k >> 1; j > 0; j >>= 1) {
            uint32_t o = __shfl_xor_sync(FULL, v, j);
            bool up = ((lane & k) == 0);
            bool keepmin = (((lane & j) == 0) == up);
            v = keepmin ? umin2(v, o) : umax2(v, o);
        }
    }
    return __shfl_sync(FULL, v, 20);
}

__global__ void pospack_kernel(const float* __restrict__ x) {
    int i = blockIdx.x * 256 + threadIdx.x;
    float p0 = x[i * 6 + 0], p1 = x[i * 6 + 1], p2 = x[i * 6 + 2];
    g_pos4[i] = make_float4(p0, p1, p2, p0 * p0 + p1 * p1 + p2 * p2);
}

// ---- kNN on positions: warp per row, threshold select ----
__global__ void __launch_bounds__(256) knnsel_kernel() {
    __shared__ float4 pos[2048];                 // 32KB
    __shared__ uint2 cand[8][CANDMAX];           // 15.5KB
    const unsigned FULL = 0xffffffffu;
    int t = threadIdx.x, w = t >> 5, lane = t & 31;
    size_t rowBase = (size_t)blockIdx.x * 8;
    int b = (int)(rowBase >> 11);
    const float4* P = g_pos4 + (size_t)b * NN;
    for (int i = t; i < 2048; i += 256) pos[i] = P[i];
    __syncthreads();
    size_t row = rowBase + w;
    float4 q = pos[(int)(row & 2047)];
    // pass 1: per-lane min over 64 keys
    uint32_t mn = 0xffffffffu;
#pragma unroll
    for (int i = 0; i < 64; ++i) {
        float4 p = pos[i * 32 + lane];
        float inner = q.x * p.x + q.y * p.y + q.z * p.z;
        uint32_t key = fkey(-((2.0f * inner - q.w) - p.w));
        mn = umin2(mn, key);
    }
    uint32_t T = warp_rank20(mn, lane);          // T >= true 20th value (provable)
    // pass 2: collect candidates (key <= T) via ballot prefix, no atomics
    unsigned lmask = (1u << lane) - 1u;
    int base = 0;
#pragma unroll
    for (int i = 0; i < 64; ++i) {
        float4 p = pos[i * 32 + lane];
        float inner = q.x * p.x + q.y * p.y + q.z * p.z;
        uint32_t key = fkey(-((2.0f * inner - q.w) - p.w));
        bool le = key <= T;
        unsigned bal = __ballot_sync(FULL, le);
        int pp = base + __popc(bal & lmask);
        if (le && pp < CANDMAX) cand[w][pp] = make_uint2(key, (uint32_t)(i * 32 + lane));
        base += __popc(bal);
    }
    __syncwarp();
    int* out = g_idx + row * KNN;
    if (base <= CANDMAX) {
        // exact rank over candidates: strict (value, index) order -> unique ranks
        for (int j = lane; j < base; j += 32) {
            uint2 cj = cand[w][j];
            int r = 0;
            for (int i = 0; i < base; ++i) {
                uint2 ci = cand[w][i];
                r += (ci.x < cj.x || (ci.x == cj.x && ci.y < cj.y)) ? 1 : 0;
            }
            if (r < KNN) out[r] = (int)cj.y;
        }
    } else {
        // exact fallback: binary search the 20th value, then ordered emission
        uint32_t lo = 0, hi = 0xffffffffu;
        while (lo < hi) {
            uint32_t mid = lo + ((hi - lo) >> 1);
            int cnt = 0;
            for (int i = 0; i < 64; ++i) {
                float4 p = pos[i * 32 + lane];
                float inner = q.x * p.x + q.y * p.y + q.z * p.z;
                uint32_t key = fkey(-((2.0f * inner - q.w) - p.w));
                cnt += (key <= mid) ? 1 : 0;
            }
#pragma unroll
            for (int off = 16; off; off >>= 1) cnt += __shfl_xor_sync(FULL, cnt, off);
            if (cnt >= KNN) hi = mid; else lo = mid + 1;
        }
        uint32_t T20 = hi;
        int a = 0;
        for (int i = 0; i < 64; ++i) {
            float4 p = pos[i * 32 + lane];
            float inner = q.x * p.x + q.y * p.y + q.z * p.z;
            uint32_t key = fkey(-((2.0f * inner - q.w) - p.w));
            bool lt = key < T20;
            unsigned bal = __ballot_sync(FULL, lt);
            int pp = a + __popc(bal & lmask);
            if (lt) out[pp] = i * 32 + lane;
            a += __popc(bal);
        }
        int taken = 0;
        for (int i = 0; i < 64 && a + taken < KNN; ++i) {
            float4 p = pos[i * 32 + lane];
            float inner = q.x * p.x + q.y * p.y + q.z * p.z;
            uint32_t key = fkey(-((2.0f * inner - q.w) - p.w));
            bool eq = key == T20;
            unsigned bal = __ballot_sync(FULL, eq);
            int pp = a + taken + __popc(bal & lmask);
            if (eq && pp < KNN) out[pp] = i * 32 + lane;
            taken += __popc(bal);
        }
    }
}

// ---- top-k over materialized keys: warp per row, threshold select ----
__global__ void __launch_bounds__(256) topksel_kernel() {
    __shared__ uint2 cand[8][CANDMAX];
    const unsigned FULL = 0xffffffffu;
    int t = threadIdx.x, w = t >> 5, lane = t & 31;
    size_t row = (size_t)blockIdx.x * 8 + w;
    const uint4* D = (const uint4*)(g_big + row * NN);
    uint32_t mn = 0xffffffffu;
#pragma unroll
    for (int j = 0; j < 16; ++j) {
        uint4 v = D[j * 32 + lane];
        mn = umin2(mn, umin2(umin2(v.x, v.y), umin2(v.z, v.w)));
    }
    uint32_t T = warp_rank20(mn, lane);
    unsigned lmask = (1u << lane) - 1u;
    int base = 0;
#pragma unroll
    for (int j = 0; j < 16; ++j) {
        uint4 v = D[j * 32 + lane];
        int bi = (j * 32 + lane) * 4;
        uint32_t ks[4] = {v.x, v.y, v.z, v.w};
#pragma unroll
        for (int c2 = 0; c2 < 4; ++c2) {
            bool le = ks[c2] <= T;
            unsigned bal = __ballot_sync(FULL, le);
            int pp = base + __popc(bal & lmask);
            if (le && pp < CANDMAX) cand[w][pp] = make_uint2(ks[c2], (uint32_t)(bi + c2));
            base += __popc(bal);
        }
    }
    __syncwarp();
    int* out = g_idx + row * KNN;
    if (base <= CANDMAX) {
        for (int j = lane; j < base; j += 32) {
            uint2 cj = cand[w][j];
            int r = 0;
            for (int i = 0; i < base; ++i) {
                uint2 ci = cand[w][i];
                r += (ci.x < cj.x || (ci.x == cj.x && ci.y < cj.y)) ? 1 : 0;
            }
            if (r < KNN) out[r] = (int)cj.y;
        }
    } else {
        const uint32_t* Dr = g_big + row * NN;
        uint32_t lo = 0, hi = 0xffffffffu;
        while (lo < hi) {
            uint32_t mid = lo + ((hi - lo) >> 1);
            int cnt = 0;
            for (int i = lane; i < NN; i += 32) cnt += (Dr[i] <= mid) ? 1 : 0;
#pragma unroll
            for (int off = 16; off; off >>= 1) cnt += __shfl_xor_sync(FULL, cnt, off);
            if (cnt >= KNN) hi = mid; else lo = mid + 1;
        }
        uint32_t T20 = hi;
        int a = 0;
        for (int i0 = 0; i0 < NN; i0 += 32) {
            uint32_t key = Dr[i0 + lane];
            bool lt = key < T20;
            unsigned bal = __ballot_sync(FULL, lt);
            int pp = a + __popc(bal & lmask);
            if (lt) out[pp] = i0 + lane;
            a += __popc(bal);
        }
        int taken = 0;
        for (int i0 = 0; i0 < NN && a + taken < KNN; i0 += 32) {
            uint32_t key = Dr[i0 + lane];
            bool eq = key == T20;
            unsigned bal = __ballot_sync(FULL, eq);
            int pp = a + taken + __popc(bal & lmask);
            if (eq && pp < KNN) out[pp] = i0 + lane;
            taken += __popc(bal);
        }
    }
}

__global__ void pq1_kernel(const float* __restrict__ x, const float* __restrict__ W) {
    __shared__ float xsh[4][3];
    int pt = threadIdx.x >> 6, o = threadIdx.x & 63;
    size_t p = (size_t)blockIdx.x * 4 + pt;
    if (o < 3) xsh[pt][o] = x[p * 6 + o];
    __syncthreads();
    float sp = 0.f, sqv = 0.f;
#pragma unroll
    for (int c = 0; c < 3; ++c) {
        float xv = xsh[pt][c];
        float wd = W[o * 6 + c], wc = W[o * 6 + 3 + c];
        sp += xv * wd; sqv += xv * (wc - wd);
    }
    g_P[p * 64 + o] = sp;
    g_Q[p * 64 + o] = sqv;
}

__global__ void pq2_kernel(const float* __restrict__ W) {
    __shared__ float wd[64 * 65];
    __shared__ float wq[64 * 65];
    __shared__ float xsh[4][64];
    int t = threadIdx.x;
#pragma unroll
    for (int it = 0; it < 16; ++it) {
        int idx = t + it * 256;
        int c = idx & 63, o = idx >> 6;
        float a = W[o * 128 + c], bq = W[o * 128 + 64 + c];
        wd[c * 65 + o] = a;
        wq[c * 65 + o] = bq - a;
    }
    int pt = t >> 6, o = t & 63;
    size_t p = (size_t)blockIdx.x * 4 + pt;
    xsh[pt][o] = g_h[p * 128 + o];
    __syncthreads();
    float sp = 0.f, sqv = 0.f;
#pragma unroll 8
    for (int c = 0; c < 64; ++c) {
        float xv = xsh[pt][c];
        sp += xv * wd[c * 65 + o];
        sqv += xv * wq[c * 65 + o];
    }
    g_P[p * 64 + o] = sp;
    g_Q[p * 64 + o] = sqv;
}

__global__ void gather_kernel(int withSq, int outOff) {
    __shared__ int idxs[4][KNN];
    __shared__ float part[8];
    int pt = threadIdx.x >> 6, o = threadIdx.x & 63;
    size_t p = (size_t)blockIdx.x * 4 + pt;
    int b = (int)(p >> 11);
    if (o < KNN) idxs[pt][o] = g_idx[p * KNN + o];
    __syncthreads();
    float q = g_Q[p * 64 + o];
    float best = -FINF;
#pragma unroll
    for (int k = 0; k < KNN; ++k) {
        int m = idxs[pt][k];
        best = fmaxf(best, g_P[((size_t)b * NN + m) * 64 + o] + q);
    }
    best = lrelu(best);
    g_h[p * 128 + outOff + o] = best;
    if (withSq) {
        float s = best * best;
#pragma unroll
        for (int off = 16; off; off >>= 1) s += __shfl_xor_sync(0xffffffffu, s, off);
        if ((threadIdx.x & 31) == 0) part[threadIdx.x >> 5] = s;
        __syncthreads();
        if (o == 0) g_sq[p] = part[pt * 2] + part[pt * 2 + 1];
    }
}

__global__ void __launch_bounds__(256, 2) gram2_kernel() {
    extern __shared__ float sh[];
    float* As = sh;
    float* Bs = sh + 64 * 132;
    int b = blockIdx.y;
    int p = blockIdx.x;
    int ti = 0;
    while (p >= 16 - ti) { p -= 16 - ti; ++ti; }
    int tj = ti + p;
    int nBase = ti * 128, mBase = tj * 128;
    const float* X = g_h + (size_t)b * NN * 128;
    int tid = threadIdx.x;
#pragma unroll
    for (int it = 0; it < 32; ++it) {
        int idx = tid + it * 256;
        int r = idx >> 6, k = idx & 63;
        As[k * 132 + r] = X[(size_t)(nBase + r) * 128 + k];
        Bs[k * 132 + r] = X[(size_t)(mBase + r) * 128 + k];
    }
    __syncthreads();
    int tx = tid & 15, ty = tid >> 4;
    float acc[8][8] = {};
#pragma unroll 8
    for (int k = 0; k < 64; ++k) {
        float4 a0 = *(const float4*)&As[k * 132 + ty * 4];
        float4 a1 = *(const float4*)&As[k * 132 + 64 + ty * 4];
        float4 b0 = *(const float4*)&Bs[k * 132 + tx * 4];
        float4 b1 = *(const float4*)&Bs[k * 132 + 64 + tx * 4];
        float av[8] = {a0.x, a0.y, a0.z, a0.w, a1.x, a1.y, a1.z, a1.w};
        float bv[8] = {b0.x, b0.y, b0.z, b0.w, b1.x, b1.y, b1.z, b1.w};
#pragma unroll
        for (int u = 0; u < 8; ++u)
#pragma unroll
            for (int v = 0; v < 8; ++v) acc[u][v] += av[u] * bv[v];
    }
    const float* sqb = g_sq + b * NN;
    int rl[8], cl[8];
#pragma unroll
    for (int u = 0; u < 8; ++u) {
        rl[u] = (u < 4) ? ty * 4 + u : 64 + ty * 4 + (u - 4);
        cl[u] = (u < 4) ? tx * 4 + u : 64 + tx * 4 + (u - 4);
    }
    float qn[8], qm[8];
#pragma unroll
    for (int u = 0; u < 8; ++u) { qn[u] = sqb[nBase + rl[u]]; qm[u] = sqb[mBase + cl[u]]; }
#pragma unroll
    for (int u = 0; u < 8; ++u) {
        uint4 w0, w1;
        w0.x = fkey(-((2.0f * acc[u][0] - qn[u]) - qm[0]));
        w0.y = fkey(-((2.0f * acc[u][1] - qn[u]) - qm[1]));
        w0.z = fkey(-((2.0f * acc[u][2] - qn[u]) - qm[2]));
        w0.w = fkey(-((2.0f * acc[u][3] - qn[u]) - qm[3]));
        w1.x = fkey(-((2.0f * acc[u][4] - qn[u]) - qm[4]));
        w1.y = fkey(-((2.0f * acc[u][5] - qn[u]) - qm[5]));
        w1.z = fkey(-((2.0f * acc[u][6] - qn[u]) - qm[6]));
        w1.w = fkey(-((2.0f * acc[u][7] - qn[u]) - qm[7]));
        size_t base = ((size_t)b * NN + nBase + rl[u]) * NN + mBase;
        *(uint4*)&g_big[base + tx * 4]      = w0;
        *(uint4*)&g_big[base + 64 + tx * 4] = w1;
    }
    if (ti != tj) {
        __syncthreads();
        uint32_t* tru = (uint32_t*)sh;
#pragma unroll
        for (int u = 0; u < 8; ++u)
#pragma unroll
            for (int v = 0; v < 8; ++v)
                tru[cl[v] * 132 + rl[u]] = fkey(-((2.0f * acc[u][v] - qm[v]) - qn[u]));
        __syncthreads();
#pragma unroll
        for (int it = 0; it < 16; ++it) {
            int idx = tid + it * 256;
            int r = idx >> 5, c4 = idx & 31;
            uint4 wv = *(uint4*)&tru[r * 132 + c4 * 4];
            *(uint4*)&g_big[((size_t)b * NN + mBase + r) * NN + nBase + c4 * 4] = wv;
        }
    }
}

__global__ void __launch_bounds__(256, 2) w5p_kernel(const float* __restrict__ W5) {
    extern __shared__ float sh[];
    float* As = sh;
    float* Bs = sh + 64 * 132;
    int oBase = blockIdx.x * 128;
    int rt = blockIdx.y;
    int b  = blockIdx.z;
    size_t rowBase = (size_t)b * NN + rt * 128;
    int tid = threadIdx.x, tx = tid & 15, ty = tid >> 4;
    float acc[8][8] = {};
    for (int kb = 0; kb < 128; kb += 64) {
        __syncthreads();
#pragma unroll
        for (int it = 0; it < 32; ++it) {
            int idx = tid + it * 256;
            int r = idx >> 6, k = idx & 63;
            As[k * 132 + r] = g_h[(rowBase + r) * 128 + kb + k];
            Bs[k * 132 + r] = W5[(size_t)(oBase + r) * 128 + kb + k];
        }
        __syncthreads();
#pragma unroll 8
        for (int k = 0; k < 64; ++k) {
            float4 a0 = *(const float4*)&As[k * 132 + ty * 4];
            float4 a1 = *(const float4*)&As[k * 132 + 64 + ty * 4];
            float4 b0 = *(const float4*)&Bs[k * 132 + tx * 4];
            float4 b1 = *(const float4*)&Bs[k * 132 + 64 + tx * 4];
            float av[8] = {a0.x, a0.y, a0.z, a0.w, a1.x, a1.y, a1.z, a1.w};
            float bv[8] = {b0.x, b0.y, b0.z, b0.w, b1.x, b1.y, b1.z, b1.w};
#pragma unroll
            for (int u = 0; u < 8; ++u)
#pragma unroll
                for (int v = 0; v < 8; ++v) acc[u][v] += av[u] * bv[v];
        }
    }
    float cmax[8], csum[8];
#pragma unroll
    for (int v = 0; v < 8; ++v) { cmax[v] = -FINF; csum[v] = 0.f; }
#pragma unroll
    for (int u = 0; u < 8; ++u)
#pragma unroll
        for (int v = 0; v < 8; ++v) {
            float val = lrelu(acc[u][v]);
            cmax[v] = fmaxf(cmax[v], val);
            csum[v] += val;
        }
    __syncthreads();
    float* pmax = sh;
    float* psum = sh + 16 * 128;
#pragma unroll
    for (int v = 0; v < 8; ++v) {
        int c = (v < 4) ? tx * 4 + v : 64 + tx * 4 + (v - 4);
        pmax[ty * 128 + c] = cmax[v];
        psum[ty * 128 + c] = csum[v];
    }
    __syncthreads();
    if (tid < 128) {
        float m = -FINF, s = 0.f;
#pragma unroll
        for (int t2 = 0; t2 < 16; ++t2) {
            m = fmaxf(m, pmax[t2 * 128 + tid]);
            s += psum[t2 * 128 + tid];
        }
        size_t o = ((size_t)b * 16 + rt) * 1024 + oBase + tid;
        g_pmax[o] = m;
        g_psum[o] = s;
    }
}

__global__ void hreduce_kernel() {
    int t = blockIdx.x * 256 + threadIdx.x;
    int b = t >> 10, c = t & 1023;
    float m = -FINF, s = 0.f;
#pragma unroll
    for (int tile = 0; tile < 16; ++tile) {
        size_t idx = ((size_t)b * 16 + tile) * 1024 + c;
        m = fmaxf(m, g_pmax[idx]);
        s += g_psum[idx];
    }
    g_red[b * 1024 + c]         = m;
    g_red[32768 + b * 1024 + c] = s * (1.0f / NN);
}

__global__ void fbranch2_kernel(const float* __restrict__ x,
                                const float* __restrict__ W3,
                                const float* __restrict__ W4) {
    __shared__ float w3s[96];
    __shared__ float w4t[32 * 64];
    __shared__ float f1s[32][33];
    __shared__ float rmx[4][64], rsm[4][64];
    int b = blockIdx.x, t = threadIdx.x;
    if (t < 96) w3s[t] = W3[t];
    for (int it = t; it < 2048; it += 256) {
        int o = it & 63, j = it >> 6;
        w4t[j * 64 + o] = W4[o * 32 + j];
    }
    int o = t & 63, pg = t >> 6;
    float mx = -FINF, sm = 0.f;
    for (int n0 = 0; n0 < NN; n0 += 32) {
        __syncthreads();
#pragma unroll
        for (int e = 0; e < 4; ++e) {
            int idx = t + e * 256;
            int pp = idx >> 5, oo = idx & 31;
            const float* xp = x + ((size_t)b * NN + n0 + pp) * 6 + 3;
            float s = xp[0] * w3s[oo * 3] + xp[1] * w3s[oo * 3 + 1] + xp[2] * w3s[oo * 3 + 2];
            f1s[pp][oo] = lrelu(s);
        }
        __syncthreads();
#pragma unroll
        for (int q = 0; q < 8; ++q) {
            int pp = pg * 8 + q;
            float s = 0.f;
#pragma unroll
            for (int j2 = 0; j2 < 32; ++j2) s += f1s[pp][j2] * w4t[j2 * 64 + o];
            s = lrelu(s);
            mx = fmaxf(mx, s);
            sm += s;
        }
    }
    rmx[pg][o] = mx; rsm[pg][o] = sm;
    __syncthreads();
    if (t < 64) {
        float m = fmaxf(fmaxf(rmx[0][t], rmx[1][t]), fmaxf(rmx[2][t], rmx[3][t]));
        float s = rsm[0][t] + rsm[1][t] + rsm[2][t] + rsm[3][t];
        g_red[65536 + b * 64 + t] = m;
        g_red[67584 + b * 64 + t] = s * (1.0f / NN);
    }
}

__global__ void mlp2_kernel(const float* __restrict__ L1,
                            const float* __restrict__ L2w, const float* __restrict__ L2b,
                            const float* __restrict__ L3w, const float* __restrict__ L3b,
                            float* __restrict__ out) {
    __shared__ float z[2176];
    __shared__ float z1[128];
    __shared__ float z2[64];
    int b = blockIdx.x, t = threadIdx.x, w = t >> 5, lane = t & 31;
    for (int i = t; i < 2176; i += 256) {
        float v;
        if (i < 1024)      v = g_red[b * 1024 + i];
        else if (i < 2048) v = g_red[32768 + b * 1024 + (i - 1024)];
        else if (i < 2112) v = g_red[65536 + b * 64 + (i - 2048)];
        else               v = g_red[67584 + b * 64 + (i - 2112)];
        z[i] = v;
    }
    __syncthreads();
    for (int r = w; r < 128; r += 8) {
        const float* wt = L1 + (size_t)r * 2176;
        float s = 0.f;
        for (int j = lane; j < 2176; j += 32) s += z[j] * wt[j];
#pragma unroll
        for (int off = 16; off; off >>= 1) s += __shfl_xor_sync(0xffffffffu, s, off);
        if (lane == 0) z1[r] = lrelu(s);
    }
    __syncthreads();
    for (int r = w; r < 64; r += 8) {
        float s = 0.f;
#pragma unroll
        for (int j = lane; j < 128; j += 32) s += z1[j] * L2w[r * 128 + j];
#pragma unroll
        for (int off = 16; off; off >>= 1) s += __shfl_xor_sync(0xffffffffu, s, off);
        if (lane == 0) z2[r] = lrelu(s + L2b[r]);
    }
    __syncthreads();
    for (int r = w; r < 40; r += 8) {
        float s = 0.f;
#pragma unroll
        for (int j = lane; j < 64; j += 32) s += z2[j] * L3w[r * 64 + j];
#pragma unroll
        for (int off = 16; off; off >>= 1) s += __shfl_xor_sync(0xffffffffu, s, off);
        if (lane == 0) out[b * 40 + r] = s + L3b[r];
    }
}

extern "C" void kernel_launch(void* const* d_in, const int* in_sizes, int n_in,
                              void* d_out, int out_size) {
    const float* x   = (const float*)d_in[0];
    const float* W1  = (const float*)d_in[1];
    const float* W2  = (const float*)d_in[2];
    const float* W5  = (const float*)d_in[3];
    const float* W3  = (const float*)d_in[4];
    const float* W4  = (const float*)d_in[5];
    const float* L1  = (const float*)d_in[6];
    const float* L2w = (const float*)d_in[7];
    const float* L2b = (const float*)d_in[8];
    const float* L3w = (const float*)d_in[9];
    const float* L3b = (const float*)d_in[10];
    float* out = (float*)d_out;

    const int PTS = BB * NN;
    const int GEMM_SMEM = 2 * 64 * 132 * (int)sizeof(float);
    static int attrDone = 0;
    if (!attrDone) {
        cudaFuncSetAttribute(gram2_kernel, cudaFuncAttributeMaxDynamicSharedMemorySize, GEMM_SMEM);
        cudaFuncSetAttribute(w5p_kernel,   cudaFuncAttributeMaxDynamicSharedMemorySize, GEMM_SMEM);
        attrDone = 1;
    }

    // order keeps knnsel at capture slot (index 3) for ncu attribution
    pospack_kernel<<<PTS / 256, 256>>>(x);
    pq1_kernel<<<PTS / 4, 256>>>(x, W1);
    fbranch2_kernel<<<BB, 256>>>(x, W3, W4);
    knnsel_kernel<<<PTS / 8, 256>>>();
    gather_kernel<<<PTS / 4, 256>>>(1, 0);
    { dim3 grid(136, BB); gram2_kernel<<<grid, 256, GEMM_SMEM>>>(); }
    topksel_kernel<<<PTS / 8, 256>>>();
    pq2_kernel<<<PTS / 4, 256>>>(W2);
    gather_kernel<<<PTS / 4, 256>>>(0, 64);
    { dim3 grid(8, 16, BB); w5p_kernel<<<grid, 256, GEMM_SMEM>>>(W5); }
    hreduce_kernel<<<128, 256>>>();
    mlp2_kernel<<<BB, 256>>>(L1, L2w, L2b, L3w, L3b, out);
}

// round 17
// speedup vs baseline: 1.8498x; 1.0492x over previous
#include <cuda_runtime.h>
#include <cstdint>

#define BB   32
#define NN   2048
#define KNN  20
#define CANDMAX 248

static __device__ __forceinline__ float lrelu(float v) { return v >= 0.0f ? v : 0.2f * v; }
#define FINF __int_as_float(0x7f800000)

__device__ uint32_t g_big[(size_t)BB * NN * NN];  // order-preserving dist keys (smaller = nearer)
__device__ float g_h  [(size_t)BB * NN * 128];
__device__ float g_P  [(size_t)BB * NN * 64];
__device__ float g_Q  [(size_t)BB * NN * 64];
__device__ float g_sq [BB * NN];
__device__ int   g_idx[BB * NN * KNN];
__device__ float4 g_pos4[BB * NN];
__device__ float g_pmax[(size_t)BB * 16 * 1024];
__device__ float g_psum[(size_t)BB * 16 * 1024];
__device__ float g_red[2 * BB * 1024 + 2 * BB * 64];

static __device__ __forceinline__ uint32_t fkey(float f) {
    uint32_t u = __float_as_uint(f);
    return (u & 0x80000000u) ? ~u : (u | 0x80000000u);
}

static __device__ __forceinline__ uint32_t umin2(uint32_t a, uint32_t b) { return a < b ? a : b; }
static __device__ __forceinline__ uint32_t umax2(uint32_t a, uint32_t b) { return a > b ? a : b; }

// ascending bitonic sort of one value per lane; returns rank-20 value (0-based)
static __device__ __forceinline__ uint32_t warp_rank20(uint32_t v, int lane) {
    const unsigned FULL = 0xffffffffu;
#pragma unroll
    for (int k = 2; k <= 32; k <<= 1) {
#pragma unroll
        for (int j = k >> 1; j > 0; j >>= 1) {
            uint32_t o = __shfl_xor_sync(FULL, v, j);
            bool up = ((lane & k) == 0);
            bool keepmin = (((lane & j) == 0) == up);
            v = keepmin ? umin2(v, o) : umax2(v, o);
        }
    }
    return __shfl_sync(FULL, v, 20);
}

__global__ void pospack_kernel(const float* __restrict__ x) {
    int i = blockIdx.x * 256 + threadIdx.x;
    float p0 = x[i * 6 + 0], p1 = x[i * 6 + 1], p2 = x[i * 6 + 2];
    g_pos4[i] = make_float4(p0, p1, p2, p0 * p0 + p1 * p1 + p2 * p2);
}

// exact fallback for knn (astronomically rare): binary-search T20, ordered emission
static __device__ __noinline__ void knn_fallback(const float4* pos, float4 q, int lane, int* out) {
    const unsigned FULL = 0xffffffffu;
    unsigned lmask = (1u << lane) - 1u;
    uint32_t lo = 0, hi = 0xffffffffu;
    while (lo < hi) {
        uint32_t mid = lo + ((hi - lo) >> 1);
        int cnt = 0;
#pragma unroll 4
        for (int i = 0; i < 64; ++i) {
            float4 p = pos[i * 32 + lane];
            float inner = q.x * p.x + q.y * p.y + q.z * p.z;
            cnt += (fkey(-((2.0f * inner - q.w) - p.w)) <= mid) ? 1 : 0;
        }
#pragma unroll
        for (int off = 16; off; off >>= 1) cnt += __shfl_xor_sync(FULL, cnt, off);
        if (cnt >= KNN) hi = mid; else lo = mid + 1;
    }
    uint32_t T20 = hi;
    int a = 0;
    for (int i = 0; i < 64; ++i) {
        float4 p = pos[i * 32 + lane];
        float inner = q.x * p.x + q.y * p.y + q.z * p.z;
        uint32_t key = fkey(-((2.0f * inner - q.w) - p.w));
        bool lt = key < T20;
        unsigned bal = __ballot_sync(FULL, lt);
        int pp = a + __popc(bal & lmask);
        if (lt) out[pp] = i * 32 + lane;
        a += __popc(bal);
    }
    int taken = 0;
    for (int i = 0; i < 64 && a + taken < KNN; ++i) {
        float4 p = pos[i * 32 + lane];
        float inner = q.x * p.x + q.y * p.y + q.z * p.z;
        uint32_t key = fkey(-((2.0f * inner - q.w) - p.w));
        bool eq = key == T20;
        unsigned bal = __ballot_sync(FULL, eq);
        int pp = a + taken + __popc(bal & lmask);
        if (eq && pp < KNN) out[pp] = i * 32 + lane;
        taken += __popc(bal);
    }
}

static __device__ __noinline__ void topk_fallback(const uint32_t* Dr, int lane, int* out) {
    const unsigned FULL = 0xffffffffu;
    unsigned lmask = (1u << lane) - 1u;
    uint32_t lo = 0, hi = 0xffffffffu;
    while (lo < hi) {
        uint32_t mid = lo + ((hi - lo) >> 1);
        int cnt = 0;
        for (int i = lane; i < NN; i += 32) cnt += (Dr[i] <= mid) ? 1 : 0;
#pragma unroll
        for (int off = 16; off; off >>= 1) cnt += __shfl_xor_sync(FULL, cnt, off);
        if (cnt >= KNN) hi = mid; else lo = mid + 1;
    }
    uint32_t T20 = hi;
    int a = 0;
    for (int i0 = 0; i0 < NN; i0 += 32) {
        uint32_t key = Dr[i0 + lane];
        bool lt = key < T20;
        unsigned bal = __ballot_sync(FULL, lt);
        int pp = a + __popc(bal & lmask);
        if (lt) out[pp] = i0 + lane;
        a += __popc(bal);
    }
    int taken = 0;
    for (int i0 = 0; i0 < NN && a + taken < KNN; i0 += 32) {
        uint32_t key = Dr[i0 + lane];
        bool eq = key == T20;
        unsigned bal = __ballot_sync(FULL, eq);
        int pp = a + taken + __popc(bal & lmask);
        if (eq && pp < KNN) out[pp] = i0 + lane;
        taken += __popc(bal);
    }
}

// ---- kNN on positions: warp per row, threshold select ----
__global__ void __launch_bounds__(256, 3) knnsel_kernel() {
    __shared__ float4 pos[2048];                 // 32KB
    __shared__ uint2 cand[8][CANDMAX];           // 15.5KB
    const unsigned FULL = 0xffffffffu;
    int t = threadIdx.x, w = t >> 5, lane = t & 31;
    size_t rowBase = (size_t)blockIdx.x * 8;
    int b = (int)(rowBase >> 11);
    const float4* P = g_pos4 + (size_t)b * NN;
    for (int i = t; i < 2048; i += 256) pos[i] = P[i];
    __syncthreads();
    size_t row = rowBase + w;
    float4 q = pos[(int)(row & 2047)];
    // pass 1: per-lane min over 64 keys
    uint32_t mn = 0xffffffffu;
#pragma unroll 4
    for (int i = 0; i < 64; ++i) {
        float4 p = pos[i * 32 + lane];
        float inner = q.x * p.x + q.y * p.y + q.z * p.z;
        mn = umin2(mn, fkey(-((2.0f * inner - q.w) - p.w)));
    }
    uint32_t T = warp_rank20(mn, lane);          // T >= true 20th value (provable)
    // pass 2: collect candidates (key <= T) via ballot prefix, no atomics
    unsigned lmask = (1u << lane) - 1u;
    int base = 0;
#pragma unroll 4
    for (int i = 0; i < 64; ++i) {
        float4 p = pos[i * 32 + lane];
        float inner = q.x * p.x + q.y * p.y + q.z * p.z;
        uint32_t key = fkey(-((2.0f * inner - q.w) - p.w));
        bool le = key <= T;
        unsigned bal = __ballot_sync(FULL, le);
        int pp = base + __popc(bal & lmask);
        if (le && pp < CANDMAX) cand[w][pp] = make_uint2(key, (uint32_t)(i * 32 + lane));
        base += __popc(bal);
    }
    __syncwarp();
    int* out = g_idx + row * KNN;
    if (base <= CANDMAX) {
        // exact rank over candidates: strict (value, index) order -> unique ranks
        for (int j = lane; j < base; j += 32) {
            uint2 cj = cand[w][j];
            int r = 0;
            for (int i = 0; i < base; ++i) {
                uint2 ci = cand[w][i];
                r += (ci.x < cj.x || (ci.x == cj.x && ci.y < cj.y)) ? 1 : 0;
            }
            if (r < KNN) out[r] = (int)cj.y;
        }
    } else {
        knn_fallback(pos, q, lane, out);
    }
}

// ---- top-k over materialized keys: warp per row, threshold select ----
__global__ void __launch_bounds__(256, 4) topksel_kernel() {
    __shared__ uint2 cand[8][CANDMAX];
    const unsigned FULL = 0xffffffffu;
    int t = threadIdx.x, w = t >> 5, lane = t & 31;
    size_t row = (size_t)blockIdx.x * 8 + w;
    const uint4* D = (const uint4*)(g_big + row * NN);
    uint32_t mn = 0xffffffffu;
#pragma unroll 4
    for (int j = 0; j < 16; ++j) {
        uint4 v = D[j * 32 + lane];
        mn = umin2(mn, umin2(umin2(v.x, v.y), umin2(v.z, v.w)));
    }
    uint32_t T = warp_rank20(mn, lane);
    unsigned lmask = (1u << lane) - 1u;
    int base = 0;
#pragma unroll 4
    for (int j = 0; j < 16; ++j) {
        uint4 v = D[j * 32 + lane];
        int bi = (j * 32 + lane) * 4;
        uint32_t ks[4] = {v.x, v.y, v.z, v.w};
#pragma unroll
        for (int c2 = 0; c2 < 4; ++c2) {
            bool le = ks[c2] <= T;
            unsigned bal = __ballot_sync(FULL, le);
            int pp = base + __popc(bal & lmask);
            if (le && pp < CANDMAX) cand[w][pp] = make_uint2(ks[c2], (uint32_t)(bi + c2));
            base += __popc(bal);
        }
    }
    __syncwarp();
    int* out = g_idx + row * KNN;
    if (base <= CANDMAX) {
        for (int j = lane; j < base; j += 32) {
            uint2 cj = cand[w][j];
            int r = 0;
            for (int i = 0; i < base; ++i) {
                uint2 ci = cand[w][i];
                r += (ci.x < cj.x || (ci.x == cj.x && ci.y < cj.y)) ? 1 : 0;
            }
            if (r < KNN) out[r] = (int)cj.y;
        }
    } else {
        topk_fallback(g_big + row * NN, lane, out);
    }
}

__global__ void pq1_kernel(const float* __restrict__ x, const float* __restrict__ W) {
    __shared__ float xsh[4][3];
    int pt = threadIdx.x >> 6, o = threadIdx.x & 63;
    size_t p = (size_t)blockIdx.x * 4 + pt;
    if (o < 3) xsh[pt][o] = x[p * 6 + o];
    __syncthreads();
    float sp = 0.f, sqv = 0.f;
#pragma unroll
    for (int c = 0; c < 3; ++c) {
        float xv = xsh[pt][c];
        float wd = W[o * 6 + c], wc = W[o * 6 + 3 + c];
        sp += xv * wd; sqv += xv * (wc - wd);
    }
    g_P[p * 64 + o] = sp;
    g_Q[p * 64 + o] = sqv;
}

__global__ void pq2_kernel(const float* __restrict__ W) {
    __shared__ float wd[64 * 65];
    __shared__ float wq[64 * 65];
    __shared__ float xsh[4][64];
    int t = threadIdx.x;
#pragma unroll
    for (int it = 0; it < 16; ++it) {
        int idx = t + it * 256;
        int c = idx & 63, o = idx >> 6;
        float a = W[o * 128 + c], bq = W[o * 128 + 64 + c];
        wd[c * 65 + o] = a;
        wq[c * 65 + o] = bq - a;
    }
    int pt = t >> 6, o = t & 63;
    size_t p = (size_t)blockIdx.x * 4 + pt;
    xsh[pt][o] = g_h[p * 128 + o];
    __syncthreads();
    float sp = 0.f, sqv = 0.f;
#pragma unroll 8
    for (int c = 0; c < 64; ++c) {
        float xv = xsh[pt][c];
        sp += xv * wd[c * 65 + o];
        sqv += xv * wq[c * 65 + o];
    }
    g_P[p * 64 + o] = sp;
    g_Q[p * 64 + o] = sqv;
}

__global__ void gather_kernel(int withSq, int outOff) {
    __shared__ int idxs[4][KNN];
    __shared__ float part[8];
    int pt = threadIdx.x >> 6, o = threadIdx.x & 63;
    size_t p = (size_t)blockIdx.x * 4 + pt;
    int b = (int)(p >> 11);
    if (o < KNN) idxs[pt][o] = g_idx[p * KNN + o];
    __syncthreads();
    float q = g_Q[p * 64 + o];
    float best = -FINF;
#pragma unroll
    for (int k = 0; k < KNN; ++k) {
        int m = idxs[pt][k];
        best = fmaxf(best, g_P[((size_t)b * NN + m) * 64 + o] + q);
    }
    best = lrelu(best);
    g_h[p * 128 + outOff + o] = best;
    if (withSq) {
        float s = best * best;
#pragma unroll
        for (int off = 16; off; off >>= 1) s += __shfl_xor_sync(0xffffffffu, s, off);
        if ((threadIdx.x & 31) == 0) part[threadIdx.x >> 5] = s;
        __syncthreads();
        if (o == 0) g_sq[p] = part[pt * 2] + part[pt * 2 + 1];
    }
}

__global__ void __launch_bounds__(256, 2) gram2_kernel() {
    extern __shared__ float sh[];
    float* As = sh;
    float* Bs = sh + 64 * 132;
    int b = blockIdx.y;
    int p = blockIdx.x;
    int ti = 0;
    while (p >= 16 - ti) { p -= 16 - ti; ++ti; }
    int tj = ti + p;
    int nBase = ti * 128, mBase = tj * 128;
    const float* X = g_h + (size_t)b * NN * 128;
    int tid = threadIdx.x;
#pragma unroll
    for (int it = 0; it < 32; ++it) {
        int idx = tid + it * 256;
        int r = idx >> 6, k = idx & 63;
        As[k * 132 + r] = X[(size_t)(nBase + r) * 128 + k];
        Bs[k * 132 + r] = X[(size_t)(mBase + r) * 128 + k];
    }
    __syncthreads();
    int tx = tid & 15, ty = tid >> 4;
    float acc[8][8] = {};
#pragma unroll 8
    for (int k = 0; k < 64; ++k) {
        float4 a0 = *(const float4*)&As[k * 132 + ty * 4];
        float4 a1 = *(const float4*)&As[k * 132 + 64 + ty * 4];
        float4 b0 = *(const float4*)&Bs[k * 132 + tx * 4];
        float4 b1 = *(const float4*)&Bs[k * 132 + 64 + tx * 4];
        float av[8] = {a0.x, a0.y, a0.z, a0.w, a1.x, a1.y, a1.z, a1.w};
        float bv[8] = {b0.x, b0.y, b0.z, b0.w, b1.x, b1.y, b1.z, b1.w};
#pragma unroll
        for (int u = 0; u < 8; ++u)
#pragma unroll
            for (int v = 0; v < 8; ++v) acc[u][v] += av[u] * bv[v];
    }
    const float* sqb = g_sq + b * NN;
    int rl[8], cl[8];
#pragma unroll
    for (int u = 0; u < 8; ++u) {
        rl[u] = (u < 4) ? ty * 4 + u : 64 + ty * 4 + (u - 4);
        cl[u] = (u < 4) ? tx * 4 + u : 64 + tx * 4 + (u - 4);
    }
    float qn[8], qm[8];
#pragma unroll
    for (int u = 0; u < 8; ++u) { qn[u] = sqb[nBase + rl[u]]; qm[u] = sqb[mBase + cl[u]]; }
#pragma unroll
    for (int u = 0; u < 8; ++u) {
        uint4 w0, w1;
        w0.x = fkey(-((2.0f * acc[u][0] - qn[u]) - qm[0]));
        w0.y = fkey(-((2.0f * acc[u][1] - qn[u]) - qm[1]));
        w0.z = fkey(-((2.0f * acc[u][2] - qn[u]) - qm[2]));
        w0.w = fkey(-((2.0f * acc[u][3] - qn[u]) - qm[3]));
        w1.x = fkey(-((2.0f * acc[u][4] - qn[u]) - qm[4]));
        w1.y = fkey(-((2.0f * acc[u][5] - qn[u]) - qm[5]));
        w1.z = fkey(-((2.0f * acc[u][6] - qn[u]) - qm[6]));
        w1.w = fkey(-((2.0f * acc[u][7] - qn[u]) - qm[7]));
        size_t base = ((size_t)b * NN + nBase + rl[u]) * NN + mBase;
        *(uint4*)&g_big[base + tx * 4]      = w0;
        *(uint4*)&g_big[base + 64 + tx * 4] = w1;
    }
    if (ti != tj) {
        __syncthreads();
        uint32_t* tru = (uint32_t*)sh;
#pragma unroll
        for (int u = 0; u < 8; ++u)
#pragma unroll
            for (int v = 0; v < 8; ++v)
                tru[cl[v] * 132 + rl[u]] = fkey(-((2.0f * acc[u][v] - qm[v]) - qn[u]));
        __syncthreads();
#pragma unroll
        for (int it = 0; it < 16; ++it) {
            int idx = tid + it * 256;
            int r = idx >> 5, c4 = idx & 31;
            uint4 wv = *(uint4*)&tru[r * 132 + c4 * 4];
            *(uint4*)&g_big[((size_t)b * NN + mBase + r) * NN + nBase + c4 * 4] = wv;
        }
    }
}

__global__ void __launch_bounds__(256, 2) w5p_kernel(const float* __restrict__ W5) {
    extern __shared__ float sh[];
    float* As = sh;
    float* Bs = sh + 64 * 132;
    int oBase = blockIdx.x * 128;
    int rt = blockIdx.y;
    int b  = blockIdx.z;
    size_t rowBase = (size_t)b * NN + rt * 128;
    int tid = threadIdx.x, tx = tid & 15, ty = tid >> 4;
    float acc[8][8] = {};
    for (int kb = 0; kb < 128; kb += 64) {
        __syncthreads();
#pragma unroll
        for (int it = 0; it < 32; ++it) {
            int idx = tid + it * 256;
            int r = idx >> 6, k = idx & 63;
            As[k * 132 + r] = g_h[(rowBase + r) * 128 + kb + k];
            Bs[k * 132 + r] = W5[(size_t)(oBase + r) * 128 + kb + k];
        }
        __syncthreads();
#pragma unroll 8
        for (int k = 0; k < 64; ++k) {
            float4 a0 = *(const float4*)&As[k * 132 + ty * 4];
            float4 a1 = *(const float4*)&As[k * 132 + 64 + ty * 4];
            float4 b0 = *(const float4*)&Bs[k * 132 + tx * 4];
            float4 b1 = *(const float4*)&Bs[k * 132 + 64 + tx * 4];
            float av[8] = {a0.x, a0.y, a0.z, a0.w, a1.x, a1.y, a1.z, a1.w};
            float bv[8] = {b0.x, b0.y, b0.z, b0.w, b1.x, b1.y, b1.z, b1.w};
#pragma unroll
            for (int u = 0; u < 8; ++u)
#pragma unroll
                for (int v = 0; v < 8; ++v) acc[u][v] += av[u] * bv[v];
        }
    }
    float cmax[8], csum[8];
#pragma unroll
    for (int v = 0; v < 8; ++v) { cmax[v] = -FINF; csum[v] = 0.f; }
#pragma unroll
    for (int u = 0; u < 8; ++u)
#pragma unroll
        for (int v = 0; v < 8; ++v) {
            float val = lrelu(acc[u][v]);
            cmax[v] = fmaxf(cmax[v], val);
            csum[v] += val;
        }
    __syncthreads();
    float* pmax = sh;
    float* psum = sh + 16 * 128;
#pragma unroll
    for (int v = 0; v < 8; ++v) {
        int c = (v < 4) ? tx * 4 + v : 64 + tx * 4 + (v - 4);
        pmax[ty * 128 + c] = cmax[v];
        psum[ty * 128 + c] = csum[v];
    }
    __syncthreads();
    if (tid < 128) {
        float m = -FINF, s = 0.f;
#pragma unroll
        for (int t2 = 0; t2 < 16; ++t2) {
            m = fmaxf(m, pmax[t2 * 128 + tid]);
            s += psum[t2 * 128 + tid];
        }
        size_t o = ((size_t)b * 16 + rt) * 1024 + oBase + tid;
        g_pmax[o] = m;
        g_psum[o] = s;
    }
}

__global__ void hreduce_kernel() {
    int t = blockIdx.x * 256 + threadIdx.x;
    int b = t >> 10, c = t & 1023;
    float m = -FINF, s = 0.f;
#pragma unroll
    for (int tile = 0; tile < 16; ++tile) {
        size_t idx = ((size_t)b * 16 + tile) * 1024 + c;
        m = fmaxf(m, g_pmax[idx]);
        s += g_psum[idx];
    }
    g_red[b * 1024 + c]         = m;
    g_red[32768 + b * 1024 + c] = s * (1.0f / NN);
}

__global__ void fbranch2_kernel(const float* __restrict__ x,
                                const float* __restrict__ W3,
                                const float* __restrict__ W4) {
    __shared__ float w3s[96];
    __shared__ float w4t[32 * 64];
    __shared__ float f1s[32][33];
    __shared__ float rmx[4][64], rsm[4][64];
    int b = blockIdx.x, t = threadIdx.x;
    if (t < 96) w3s[t] = W3[t];
    for (int it = t; it < 2048; it += 256) {
        int o = it & 63, j = it >> 6;
        w4t[j * 64 + o] = W4[o * 32 + j];
    }
    int o = t & 63, pg = t >> 6;
    float mx = -FINF, sm = 0.f;
    for (int n0 = 0; n0 < NN; n0 += 32) {
        __syncthreads();
#pragma unroll
        for (int e = 0; e < 4; ++e) {
            int idx = t + e * 256;
            int pp = idx >> 5, oo = idx & 31;
            const float* xp = x + ((size_t)b * NN + n0 + pp) * 6 + 3;
            float s = xp[0] * w3s[oo * 3] + xp[1] * w3s[oo * 3 + 1] + xp[2] * w3s[oo * 3 + 2];
            f1s[pp][oo] = lrelu(s);
        }
        __syncthreads();
#pragma unroll
        for (int q = 0; q < 8; ++q) {
            int pp = pg * 8 + q;
            float s = 0.f;
#pragma unroll
            for (int j2 = 0; j2 < 32; ++j2) s += f1s[pp][j2] * w4t[j2 * 64 + o];
            s = lrelu(s);
            mx = fmaxf(mx, s);
            sm += s;
        }
    }
    rmx[pg][o] = mx; rsm[pg][o] = sm;
    __syncthreads();
    if (t < 64) {
        float m = fmaxf(fmaxf(rmx[0][t], rmx[1][t]), fmaxf(rmx[2][t], rmx[3][t]));
        float s = rsm[0][t] + rsm[1][t] + rsm[2][t] + rsm[3][t];
        g_red[65536 + b * 64 + t] = m;
        g_red[67584 + b * 64 + t] = s * (1.0f / NN);
    }
}

__global__ void mlp2_kernel(const float* __restrict__ L1,
                            const float* __restrict__ L2w, const float* __restrict__ L2b,
                            const float* __restrict__ L3w, const float* __restrict__ L3b,
                            float* __restrict__ out) {
    __shared__ float z[2176];
    __shared__ float z1[128];
    __shared__ float z2[64];
    int b = blockIdx.x, t = threadIdx.x, w = t >> 5, lane = t & 31;
    for (int i = t; i < 2176; i += 256) {
        float v;
        if (i < 1024)      v = g_red[b * 1024 + i];
        else if (i < 2048) v = g_red[32768 + b * 1024 + (i - 1024)];
        else if (i < 2112) v = g_red[65536 + b * 64 + (i - 2048)];
        else               v = g_red[67584 + b * 64 + (i - 2112)];
        z[i] = v;
    }
    __syncthreads();
    for (int r = w; r < 128; r += 8) {
        const float* wt = L1 + (size_t)r * 2176;
        float s = 0.f;
        for (int j = lane; j < 2176; j += 32) s += z[j] * wt[j];
#pragma unroll
        for (int off = 16; off; off >>= 1) s += __shfl_xor_sync(0xffffffffu, s, off);
        if (lane == 0) z1[r] = lrelu(s);
    }
    __syncthreads();
    for (int r = w; r < 64; r += 8) {
        float s = 0.f;
#pragma unroll
        for (int j = lane; j < 128; j += 32) s += z1[j] * L2w[r * 128 + j];
#pragma unroll
        for (int off = 16; off; off >>= 1) s += __shfl_xor_sync(0xffffffffu, s, off);
        if (lane == 0) z2[r] = lrelu(s + L2b[r]);
    }
    __syncthreads();
    for (int r = w; r < 40; r += 8) {
        float s = 0.f;
#pragma unroll
        for (int j = lane; j < 64; j += 32) s += z2[j] * L3w[r * 64 + j];
#pragma unroll
        for (int off = 16; off; off >>= 1) s += __shfl_xor_sync(0xffffffffu, s, off);
        if (lane == 0) out[b * 40 + r] = s + L3b[r];
    }
}

extern "C" void kernel_launch(void* const* d_in, const int* in_sizes, int n_in,
                              void* d_out, int out_size) {
    const float* x   = (const float*)d_in[0];
    const float* W1  = (const float*)d_in[1];
    const float* W2  = (const float*)d_in[2];
    const float* W5  = (const float*)d_in[3];
    const float* W3  = (const float*)d_in[4];
    const float* W4  = (const float*)d_in[5];
    const float* L1  = (const float*)d_in[6];
    const float* L2w = (const float*)d_in[7];
    const float* L2b = (const float*)d_in[8];
    const float* L3w = (const float*)d_in[9];
    const float* L3b = (const float*)d_in[10];
    float* out = (float*)d_out;

    const int PTS = BB * NN;
    const int GEMM_SMEM = 2 * 64 * 132 * (int)sizeof(float);
    static int attrDone = 0;
    if (!attrDone) {
        cudaFuncSetAttribute(gram2_kernel, cudaFuncAttributeMaxDynamicSharedMemorySize, GEMM_SMEM);
        cudaFuncSetAttribute(w5p_kernel,   cudaFuncAttributeMaxDynamicSharedMemorySize, GEMM_SMEM);
        attrDone = 1;
    }

    // order keeps knnsel at capture slot (index 3) for ncu attribution
    pospack_kernel<<<PTS / 256, 256>>>(x);
    pq1_kernel<<<PTS / 4, 256>>>(x, W1);
    fbranch2_kernel<<<BB, 256>>>(x, W3, W4);
    knnsel_kernel<<<PTS / 8, 256>>>();
    gather_kernel<<<PTS / 4, 256>>>(1, 0);
    { dim3 grid(136, BB); gram2_kernel<<<grid, 256, GEMM_SMEM>>>(); }
    topksel_kernel<<<PTS / 8, 256>>>();
    pq2_kernel<<<PTS / 4, 256>>>(W2);
    gather_kernel<<<PTS / 4, 256>>>(0, 64);
    { dim3 grid(8, 16, BB); w5p_kernel<<<grid, 256, GEMM_SMEM>>>(W5); }
    hreduce_kernel<<<128, 256>>>();
    mlp2_kernel<<<BB, 256>>>(L1, L2w, L2b, L3w, L3b, out);
}